// round 1
// baseline (speedup 1.0000x reference)
#include <cuda_runtime.h>
#include <cstdint>
#include <cstddef>

// Problem constants
#define BATCH 16384
#define F 512
#define NCTA 64          // scan CTAs; 64 <= 148 SMs -> all co-resident, spin-safe
#define COLS_PER_CTA 8   // output columns owned per CTA (8 warps? no: 8 cols, 1 per warp)

// Scratch (device globals: no allocation allowed in kernel_launch)
__device__ float g_xwz[(size_t)BATCH * F];   // x@Wz + bz
__device__ float g_xwh[(size_t)BATCH * F];   // x@Wh + bh
__device__ unsigned int g_count[BATCH];      // per-step completion counters

// ---------------------------------------------------------------------------
// Zero the per-step counters (must run each launch; graph replays).
// ---------------------------------------------------------------------------
__global__ void zero_counts_kernel() {
    g_count[blockIdx.x * blockDim.x + threadIdx.x] = 0u;
}

// ---------------------------------------------------------------------------
// Phase 1: batched GEMM  C = A(16384x512) * W(512x512) + bias
// blockIdx.z = 0 -> (Wz,bz)->g_xwz ; 1 -> (Wh,bh)->g_xwh
// 64x64 block tile, 256 threads, 4x4 microtile, BK=16.
// ---------------------------------------------------------------------------
#define BM 64
#define BN 64
#define BKK 16

__global__ void __launch_bounds__(256) gemm_kernel(
    const float* __restrict__ A,
    const float* __restrict__ Wz, const float* __restrict__ bz,
    const float* __restrict__ Wh, const float* __restrict__ bh)
{
    const float* B    = (blockIdx.z == 0) ? Wz : Wh;
    const float* bias = (blockIdx.z == 0) ? bz : bh;
    float*       C    = (blockIdx.z == 0) ? g_xwz : g_xwh;

    __shared__ float As[BKK][BM];
    __shared__ float Bs[BKK][BN];

    const int row0 = blockIdx.y * BM;
    const int col0 = blockIdx.x * BN;
    const int tid  = threadIdx.x;

    // A tile load mapping: 64 rows x 16 k, one float4 along k per thread
    const int a_m = tid >> 2;          // 0..63
    const int a_k = (tid & 3) * 4;     // 0,4,8,12
    // B tile load mapping: 16 k x 64 cols, one float4 along n per thread
    const int b_k = tid >> 4;          // 0..15
    const int b_n = (tid & 15) * 4;    // 0..60

    const int ty = tid >> 4;           // 0..15 -> rows ty*4..ty*4+3
    const int tx = tid & 15;           // 0..15 -> cols tx*4..tx*4+3

    float acc[4][4] = {};

    for (int k0 = 0; k0 < F; k0 += BKK) {
        float4 av = *(const float4*)(A + (size_t)(row0 + a_m) * F + k0 + a_k);
        As[a_k + 0][a_m] = av.x;
        As[a_k + 1][a_m] = av.y;
        As[a_k + 2][a_m] = av.z;
        As[a_k + 3][a_m] = av.w;
        float4 bv = *(const float4*)(B + (size_t)(k0 + b_k) * F + col0 + b_n);
        *(float4*)&Bs[b_k][b_n] = bv;
        __syncthreads();
#pragma unroll
        for (int k = 0; k < BKK; k++) {
            float ar[4], br[4];
            *(float4*)ar = *(const float4*)&As[k][ty * 4];
            *(float4*)br = *(const float4*)&Bs[k][tx * 4];
#pragma unroll
            for (int i = 0; i < 4; i++)
#pragma unroll
                for (int jj = 0; jj < 4; jj++)
                    acc[i][jj] = fmaf(ar[i], br[jj], acc[i][jj]);
        }
        __syncthreads();
    }

    float4 bv;
    bv.x = __ldg(&bias[col0 + tx * 4 + 0]);
    bv.y = __ldg(&bias[col0 + tx * 4 + 1]);
    bv.z = __ldg(&bias[col0 + tx * 4 + 2]);
    bv.w = __ldg(&bias[col0 + tx * 4 + 3]);
#pragma unroll
    for (int i = 0; i < 4; i++) {
        float4 o;
        o.x = acc[i][0] + bv.x;
        o.y = acc[i][1] + bv.y;
        o.z = acc[i][2] + bv.z;
        o.w = acc[i][3] + bv.w;
        *(float4*)(C + (size_t)(row0 + ty * 4 + i) * F + col0 + tx * 4) = o;
    }
}

// ---------------------------------------------------------------------------
// Phase 2: sequential gated scan.
// 64 CTAs x 256 threads. CTA b owns output columns j = b*8 .. b*8+7.
// Warp w (0..7) computes column j = b*8+w; lane l holds U rows l*16..l*16+15
// of both Uz[:,j] and Uh[:,j] in registers (32 floats/thread, 2MB chip-wide).
// Recurrence state m_t lives in d_out rows (out IS the ys output).
// Release: st.cg + __syncthreads + __threadfence + atomicAdd(g_count[t]).
// Acquire: lane 0 of warp 0 spins with ld.acquire.gpu on g_count[t-1].
// ---------------------------------------------------------------------------
__global__ void __launch_bounds__(256, 1) scan_kernel(
    const float* __restrict__ Uz,
    const float* __restrict__ Uh,
    float* __restrict__ out)
{
    const int b = blockIdx.x;          // 0..63
    const int w = threadIdx.x >> 5;    // warp -> column within CTA (0..7)
    const int l = threadIdx.x & 31;    // lane -> row chunk
    const int j = b * COLS_PER_CTA + w;        // global output column 0..511
    const int rbase = l * 16;                  // first U row for this lane

    // Preload this thread's U slice into registers (one-time, strided reads)
    float uz[16], uh[16];
#pragma unroll
    for (int i = 0; i < 16; i++) {
        uz[i] = Uz[(size_t)(rbase + i) * F + j];
        uh[i] = Uh[(size_t)(rbase + i) * F + j];
    }

    for (int t = 0; t < BATCH; t++) {
        // Prefetch the precomputed x@W terms (independent of the recurrence)
        float xz = 0.f, xh = 0.f;
        if (l == 0) {
            xz = __ldg(&g_xwz[(size_t)t * F + j]);
            xh = __ldg(&g_xwh[(size_t)t * F + j]);
        }

        float mv[16];
        float mj = 0.f;
        if (t > 0) {
            if (threadIdx.x == 0) {
                unsigned c;
                const unsigned* cp = &g_count[t - 1];
                do {
                    asm volatile("ld.acquire.gpu.global.u32 %0, [%1];"
                                 : "=r"(c) : "l"(cp));
                } while (c < NCTA);
            }
            __syncthreads();
            const float* mprev = out + (size_t)(t - 1) * F;
            const float4* mp = (const float4*)(mprev + rbase);
#pragma unroll
            for (int i = 0; i < 4; i++) {
                float4 v = __ldcg(mp + i);        // bypass L1: cross-SM data
                mv[i * 4 + 0] = v.x;
                mv[i * 4 + 1] = v.y;
                mv[i * 4 + 2] = v.z;
                mv[i * 4 + 3] = v.w;
            }
            if (l == 0) mj = __ldcg(mprev + j);
        } else {
#pragma unroll
            for (int i = 0; i < 16; i++) mv[i] = 0.f;
        }

        // Partial dot products against register-resident U columns
        float az = 0.f, ah = 0.f;
#pragma unroll
        for (int i = 0; i < 16; i++) {
            az = fmaf(mv[i], uz[i], az);
            ah = fmaf(mv[i], uh[i], ah);
        }
        // Warp reduce (column j fully reduced within this warp)
#pragma unroll
        for (int s = 16; s > 0; s >>= 1) {
            az += __shfl_xor_sync(0xffffffffu, az, s);
            ah += __shfl_xor_sync(0xffffffffu, ah, s);
        }

        if (l == 0) {
            float zp = az + xz;
            float hp = ah + xh;
            // sigmoid, overflow-safe
            float z = __fdividef(1.f, 1.f + __expf(-zp));
            // tanh via 1 - 2/(e^{2x}+1), overflow-safe at both ends
            float h = 1.f - __fdividef(2.f, __expf(2.f * hp) + 1.f);
            float mn = fmaf(z, h - mj, mj);
            __stcg(out + (size_t)t * F + j, mn);
        }

        __syncthreads();
        if (threadIdx.x == 0) {
            __threadfence();                   // release our CTA's 8 stores
            atomicAdd(&g_count[t], 1u);
        }
    }
}

// ---------------------------------------------------------------------------
// Launch: zero counters -> GEMMs -> persistent scan. All graph-capturable.
// ---------------------------------------------------------------------------
extern "C" void kernel_launch(void* const* d_in, const int* in_sizes, int n_in,
                              void* d_out, int out_size)
{
    const float* x  = (const float*)d_in[0];
    const float* Wz = (const float*)d_in[1];
    const float* Uz = (const float*)d_in[2];
    const float* bz = (const float*)d_in[3];
    const float* Wh = (const float*)d_in[4];
    const float* Uh = (const float*)d_in[5];
    const float* bh = (const float*)d_in[6];
    float* out = (float*)d_out;

    zero_counts_kernel<<<BATCH / 256, 256>>>();

    dim3 ggrid(F / BN, BATCH / BM, 2);   // 8 x 256 x 2
    gemm_kernel<<<ggrid, 256>>>(x, Wz, bz, Wh, bh);

    scan_kernel<<<NCTA, 256>>>(Uz, Uh, out);
}